// round 12
// baseline (speedup 1.0000x reference)
#include <cuda_runtime.h>
#include <cuda_fp16.h>
#include <cstdint>

// ---------------------------------------------------------------------------
// Single 640MB arena. Overlays (safe by sequential launch order):
//   [0,128)   P fp32 scores + in-place fp16 probs; Xh[0,8) Xl[8,16) live only
//             until k_v (k_scores then overwrites region)
//   [128,192) Qh  -> Hdh overlay (Qh dead after k_scores)
//   [192,256) Ql
//   [256,320) Kh   [320,384) Kl
//   [384,448) VTh  [448,512) VTl          (V stored TRANSPOSED [d][s] per head)
//   [512,640) weights, all pre-transposed n-major [n][k] halves:
//             WQT h/l, WKT h/l, WVT h/l (16MB each), WOT h/l (16MB each)
// ---------------------------------------------------------------------------
__device__ __align__(1024) unsigned char g_arena[(size_t)640 << 20];

#define A_P     ((size_t)0)
#define A_XH    ((size_t)0)
#define A_XL    ((size_t)8   << 20)
#define A_QH    ((size_t)128 << 20)
#define A_HDH   ((size_t)128 << 20)
#define A_QL    ((size_t)192 << 20)
#define A_KH    ((size_t)256 << 20)
#define A_KL    ((size_t)320 << 20)
#define A_VTH   ((size_t)384 << 20)
#define A_VTL   ((size_t)448 << 20)
#define A_WQTH  ((size_t)512 << 20)
#define A_WQTL  ((size_t)528 << 20)
#define A_WKTH  ((size_t)544 << 20)
#define A_WKTL  ((size_t)560 << 20)
#define A_WVTH  ((size_t)576 << 20)
#define A_WVTL  ((size_t)592 << 20)
#define A_WOTH  ((size_t)608 << 20)
#define A_WOTL  ((size_t)624 << 20)

__device__ __forceinline__ __half* PH(size_t o) { return reinterpret_cast<__half*>(g_arena + o); }
__device__ __forceinline__ float*  PF(size_t o) { return reinterpret_cast<float*>(g_arena + o); }

// ---------------------------------------------------------------------------
// helpers
// ---------------------------------------------------------------------------
__device__ __forceinline__ void mma_f16(float* d, const uint32_t* a, uint32_t b0, uint32_t b1) {
    asm volatile("mma.sync.aligned.m16n8k16.row.col.f32.f16.f16.f32 "
                 "{%0,%1,%2,%3}, {%4,%5,%6,%7}, {%8,%9}, {%0,%1,%2,%3};"
                 : "+f"(d[0]), "+f"(d[1]), "+f"(d[2]), "+f"(d[3])
                 : "r"(a[0]), "r"(a[1]), "r"(a[2]), "r"(a[3]), "r"(b0), "r"(b1));
}
__device__ __forceinline__ void ldsm4(uint32_t* r, uint32_t a) {
    asm volatile("ldmatrix.sync.aligned.m8n8.x4.shared.b16 {%0,%1,%2,%3}, [%4];"
                 : "=r"(r[0]), "=r"(r[1]), "=r"(r[2]), "=r"(r[3]) : "r"(a));
}
__device__ __forceinline__ uint32_t s2a(const void* p) {
    return (uint32_t)__cvta_generic_to_shared(p);
}
__device__ __forceinline__ uint32_t h2u(__half2 h) { return *reinterpret_cast<uint32_t*>(&h); }
__device__ __forceinline__ void split_h2(float a, float b, uint32_t& hi, uint32_t& lo) {
    __half2 h = __floats2half2_rn(a, b);
    float2 hf = __half22float2(h);
    __half2 l = __floats2half2_rn(a - hf.x, b - hf.y);
    hi = h2u(h); lo = h2u(l);
}

// ---------------------------------------------------------------------------
// fp16 GEMM: C[128x128]/CTA, Kc=16, m16n8k16, all fragments via ldmatrix.x4.
// A plain [m][k] halves (hi, +lo if ALO); B plain [n][k] halves (hi, +lo if BLO).
// Passes: hh always; hl if BLO; lh if ALO.
// smem: pitch-12-word rows (48B) -> ldmatrix phases hit banks
// {0,12,24,4,16,28,8,20}*4B: conflict-free. Single-stage, double-sync.
// EPI 0: fp32 C0;  1: fp16 hi(C0)+lo(C1);  2: fp16 hi only;  3: transposed
// fp16 hi(C0)+lo(C1) scatter (for V^T), ldc = stride of transposed rows.
// ---------------------------------------------------------------------------
template <bool ALO, bool BLO, int EPI>
__device__ __forceinline__ void gemm16(
    const __half* __restrict__ Ah, const __half* __restrict__ Al, int lda,
    const __half* __restrict__ Bh, const __half* __restrict__ Bl, int ldb,
    void* __restrict__ C0, void* __restrict__ C1, int ldc,
    int K, float alpha)
{
    __shared__ uint32_t sAh[128 * 12];
    __shared__ uint32_t sAl[ALO ? 128 * 12 : 4];
    __shared__ uint32_t sBh[128 * 12];
    __shared__ uint32_t sBl[BLO ? 128 * 12 : 4];

    const int tid = threadIdx.x, lane = tid & 31, wid = tid >> 5;
    const int g = lane >> 2, c = lane & 3;
    const int wm = wid & 1, wn = wid >> 1;
    const int row0 = blockIdx.y * 128, col0 = blockIdx.x * 128;

    // producer: thread owns one 16B piece per buffer (row tid>>1, k-half)
    const int am = tid >> 1, akh = (tid & 1) * 8;
    const __half* pAh = Ah + (size_t)(row0 + am) * lda + akh;
    const __half* pAl = ALO ? Al + (size_t)(row0 + am) * lda + akh : pAh;
    const __half* pBh = Bh + (size_t)(col0 + am) * ldb + akh;
    const __half* pBl = BLO ? Bl + (size_t)(col0 + am) * ldb + akh : pBh;
    const int so = am * 12 + (akh >> 1);

    // ldmatrix lane addresses
    //  A matrices order a0,a1,a2,a3: row-split (bit3), then word-split (bit4)
    const int arow = wm * 64 + (lane & 7) + ((lane >> 3) & 1) * 8;
    const int aoff = ((lane >> 4) & 1) * 4;
    //  B matrices order b0(nj),b1(nj),b0(nj+1),b1(nj+1): word-split (bit3), row-split (bit4)
    const int brow = wn * 32 + (lane & 7) + ((lane >> 4) & 1) * 8;
    const int boff = ((lane >> 3) & 1) * 4;
    const uint32_t adAh = s2a(sAh) + (uint32_t)(arow * 12 + aoff) * 4;
    const uint32_t adAl = s2a(sAl) + (uint32_t)(arow * 12 + aoff) * 4;
    const uint32_t adBh = s2a(sBh) + (uint32_t)(brow * 12 + boff) * 4;
    const uint32_t adBl = s2a(sBl) + (uint32_t)(brow * 12 + boff) * 4;

    uint4 rAh, rAl, rBh4, rBl4;
    const int NC = K >> 4;

    auto ldg = [&](int i) {
        rAh = *reinterpret_cast<const uint4*>(pAh + (size_t)i * 16);
        if (ALO) rAl = *reinterpret_cast<const uint4*>(pAl + (size_t)i * 16);
        rBh4 = *reinterpret_cast<const uint4*>(pBh + (size_t)i * 16);
        if (BLO) rBl4 = *reinterpret_cast<const uint4*>(pBl + (size_t)i * 16);
    };
    auto sts = [&]() {
        *reinterpret_cast<uint4*>(&sAh[so]) = rAh;
        if (ALO) *reinterpret_cast<uint4*>(&sAl[so]) = rAl;
        *reinterpret_cast<uint4*>(&sBh[so]) = rBh4;
        if (BLO) *reinterpret_cast<uint4*>(&sBl[so]) = rBl4;
    };

    float acc[4][4][4];
#pragma unroll
    for (int a = 0; a < 4; a++)
#pragma unroll
        for (int b = 0; b < 4; b++)
#pragma unroll
            for (int d = 0; d < 4; d++) acc[a][b][d] = 0.0f;

    ldg(0);
    for (int i = 0; i < NC; i++) {
        sts();
        __syncthreads();
        if (i + 1 < NC) ldg(i + 1);

        uint32_t fbh[4][2], fbl[4][2];
#pragma unroll
        for (int p = 0; p < 2; p++) {                 // p covers nj = 2p, 2p+1
            uint32_t r[4];
            ldsm4(r, adBh + p * 768);                 // 16 rows * 12 words * 4B
            fbh[2 * p][0] = r[0]; fbh[2 * p][1] = r[1];
            fbh[2 * p + 1][0] = r[2]; fbh[2 * p + 1][1] = r[3];
            if (BLO) {
                ldsm4(r, adBl + p * 768);
                fbl[2 * p][0] = r[0]; fbl[2 * p][1] = r[1];
                fbl[2 * p + 1][0] = r[2]; fbl[2 * p + 1][1] = r[3];
            }
        }
#pragma unroll
        for (int mi = 0; mi < 4; mi++) {
            uint32_t fa[4], fl[4];
            ldsm4(fa, adAh + mi * 768);
            if (ALO) ldsm4(fl, adAl + mi * 768);
#pragma unroll
            for (int nj = 0; nj < 4; nj++) {
                mma_f16(acc[mi][nj], fa, fbh[nj][0], fbh[nj][1]);            // hh
                if (BLO) mma_f16(acc[mi][nj], fa, fbl[nj][0], fbl[nj][1]);   // hl
                if (ALO) mma_f16(acc[mi][nj], fl, fbh[nj][0], fbh[nj][1]);   // lh
            }
        }
        __syncthreads();
    }

    // epilogue
#pragma unroll
    for (int mi = 0; mi < 4; mi++) {
        const int r = row0 + wm * 64 + mi * 16 + g;
#pragma unroll
        for (int nj = 0; nj < 4; nj++) {
            const int cc = col0 + wn * 32 + nj * 8 + c * 2;
            float2 v0 = make_float2(acc[mi][nj][0] * alpha, acc[mi][nj][1] * alpha);
            float2 v1 = make_float2(acc[mi][nj][2] * alpha, acc[mi][nj][3] * alpha);
            if (EPI == 0) {
                *reinterpret_cast<float2*>((float*)C0 + (size_t)r * ldc + cc)       = v0;
                *reinterpret_cast<float2*>((float*)C0 + (size_t)(r + 8) * ldc + cc) = v1;
            } else if (EPI == 3) {
                // transposed: out[cc][r], out[cc+1][r], rows stride ldc
                __half h00 = __float2half_rn(v0.x), h01 = __float2half_rn(v0.y);
                __half h10 = __float2half_rn(v1.x), h11 = __float2half_rn(v1.y);
                __half* oh = (__half*)C0;
                __half* ol = (__half*)C1;
                oh[(size_t)cc * ldc + r]           = h00;
                oh[(size_t)(cc + 1) * ldc + r]     = h01;
                oh[(size_t)cc * ldc + r + 8]       = h10;
                oh[(size_t)(cc + 1) * ldc + r + 8] = h11;
                ol[(size_t)cc * ldc + r]           = __float2half_rn(v0.x - __half2float(h00));
                ol[(size_t)(cc + 1) * ldc + r]     = __float2half_rn(v0.y - __half2float(h01));
                ol[(size_t)cc * ldc + r + 8]       = __float2half_rn(v1.x - __half2float(h10));
                ol[(size_t)(cc + 1) * ldc + r + 8] = __float2half_rn(v1.y - __half2float(h11));
            } else {
                __half2 h0 = __floats2half2_rn(v0.x, v0.y);
                __half2 h1 = __floats2half2_rn(v1.x, v1.y);
                *reinterpret_cast<__half2*>((__half*)C0 + (size_t)r * ldc + cc)       = h0;
                *reinterpret_cast<__half2*>((__half*)C0 + (size_t)(r + 8) * ldc + cc) = h1;
                if (EPI == 1) {
                    float2 f0 = __half22float2(h0), f1 = __half22float2(h1);
                    __half2 l0 = __floats2half2_rn(v0.x - f0.x, v0.y - f0.y);
                    __half2 l1 = __floats2half2_rn(v1.x - f1.x, v1.y - f1.y);
                    *reinterpret_cast<__half2*>((__half*)C1 + (size_t)r * ldc + cc)       = l0;
                    *reinterpret_cast<__half2*>((__half*)C1 + (size_t)(r + 8) * ldc + cc) = l1;
                }
            }
        }
    }
}

// ---------------------------------------------------------------------------
// GEMM wrapper kernels
// ---------------------------------------------------------------------------
// Q/K projections: fp16x3 (score path), split epilogue. B = W^T n-major.
__global__ __launch_bounds__(256, 2) void k_qk()
{
    const int z = blockIdx.z, sel = z >> 3, h = z & 7;
    const __half* Wh = PH(sel == 0 ? A_WQTH : A_WKTH) + (size_t)h * 1048576;
    const __half* Wl = PH(sel == 0 ? A_WQTL : A_WKTL) + (size_t)h * 1048576;
    __half* Ch = PH(sel == 0 ? A_QH : A_KH) + (size_t)h * 4194304;
    __half* Cl = PH(sel == 0 ? A_QL : A_KL) + (size_t)h * 4194304;
    gemm16<true, true, 1>(PH(A_XH), PH(A_XL), 1024, Wh, Wl, 1024,
                          Ch, Cl, 1024, 1024, 1.0f);
}

// V projection: 2-pass Xh*(Wh+Wl); EPI3 writes V TRANSPOSED [d][s] hi/lo
__global__ __launch_bounds__(256, 2) void k_v()
{
    const int h = blockIdx.z;
    gemm16<false, true, 3>(PH(A_XH), nullptr, 1024,
                           PH(A_WVTH) + (size_t)h * 1048576,
                           PH(A_WVTL) + (size_t)h * 1048576, 1024,
                           PH(A_VTH) + (size_t)h * 4194304,
                           PH(A_VTL) + (size_t)h * 4194304, 4096, 1024, 1.0f);
}

// scores: fp16x3; B = K rows (natively n-major); fp32 out over dead X region
__global__ __launch_bounds__(256, 2) void k_scores()
{
    const size_t z = blockIdx.z;   // h*4 + b
    gemm16<true, true, 0>(PH(A_QH) + z * 1048576, PH(A_QL) + z * 1048576, 1024,
                          PH(A_KH) + z * 1048576, PH(A_KL) + z * 1048576, 1024,
                          PF(A_P) + z * 1048576, nullptr, 1024, 1024, 32.0f);
}

// P@V: 2-pass Ph*(VTh+VTl); Ph row-strided 2048; B = V^T n-major; Hdh over Qh
__global__ __launch_bounds__(256, 2) void k_av()
{
    const int z = blockIdx.z, h = z >> 2, b = z & 3;
    __half* Ch = PH(A_HDH) + (size_t)b * 8388608 + (size_t)h * 1024;
    gemm16<false, true, 2>(PH(A_P) + (size_t)z * 2097152, nullptr, 2048,
                           PH(A_VTH) + (size_t)h * 4194304 + (size_t)b * 1024,
                           PH(A_VTL) + (size_t)h * 4194304 + (size_t)b * 1024, 4096,
                           Ch, nullptr, 8192, 1024, 1.0f);
}

// output projection: 2-pass Hdh*(WOTh+WOTl), fp32 out; B = WO^T n-major
__global__ __launch_bounds__(256, 2) void k_out(float* __restrict__ out)
{
    gemm16<false, true, 0>(PH(A_HDH), nullptr, 8192,
                           PH(A_WOTH), PH(A_WOTL), 8192,
                           out, nullptr, 1024, 8192, 1.0f);
}

// ---------------------------------------------------------------------------
// prep kernels
// ---------------------------------------------------------------------------
__global__ void k_splitX(const float* __restrict__ X)
{
    const int i = blockIdx.x * 256 + threadIdx.x;   // 1M float4
    float4 v = reinterpret_cast<const float4*>(X)[i];
    uint32_t h0, l0, h1, l1;
    split_h2(v.x, v.y, h0, l0);
    split_h2(v.z, v.w, h1, l1);
    reinterpret_cast<uint2*>(PH(A_XH))[i] = make_uint2(h0, h1);
    reinterpret_cast<uint2*>(PH(A_XL))[i] = make_uint2(l0, l1);
}

// transpose + split: W fp32 [R=k][C=n] (per z) -> W^T halves [C][R] hi/lo
__global__ void k_splitWT(const float* __restrict__ W, size_t zIn, int C, int R,
                          size_t ohOff, size_t olOff, size_t zOut)
{
    __shared__ float t[32][33];
    const float* w = W + (size_t)blockIdx.z * zIn;
    __half* oh = PH(ohOff) + (size_t)blockIdx.z * zOut;
    __half* ol = PH(olOff) + (size_t)blockIdx.z * zOut;
    const int r0 = blockIdx.y * 32, c0 = blockIdx.x * 32;
    const int tx = threadIdx.x, ty = threadIdx.y;
#pragma unroll
    for (int i = ty; i < 32; i += 8)
        t[i][tx] = w[(size_t)(r0 + i) * C + c0 + tx];
    __syncthreads();
#pragma unroll
    for (int i = ty; i < 32; i += 8) {
        float v = t[tx][i];                           // element (k=r0+tx, n=c0+i)
        __half h = __float2half_rn(v);
        __half l = __float2half_rn(v - __half2float(h));
        const size_t o = (size_t)(c0 + i) * R + r0 + tx;
        oh[o] = h; ol[o] = l;
    }
}

// ---------------------------------------------------------------------------
// softmax: fp32 scores row -> fp16 probs IN PLACE (row r at byte 4096*r)
// ---------------------------------------------------------------------------
__global__ void k_softmax()
{
    __shared__ float red[8];
    const size_t row = blockIdx.x;
    const float* p = PF(A_P) + row * 1024;
    const int t = threadIdx.x;

    float4 x = reinterpret_cast<const float4*>(p)[t];
    float m = fmaxf(fmaxf(x.x, x.y), fmaxf(x.z, x.w));
#pragma unroll
    for (int o = 16; o; o >>= 1) m = fmaxf(m, __shfl_xor_sync(0xffffffffu, m, o));
    if ((t & 31) == 0) red[t >> 5] = m;
    __syncthreads();
    if (t < 8) {
        float mm = red[t];
#pragma unroll
        for (int o = 4; o; o >>= 1) mm = fmaxf(mm, __shfl_xor_sync(0xffu, mm, o));
        red[t] = mm;
    }
    __syncthreads();
    m = red[0];
    __syncthreads();

    x.x = expf(x.x - m); x.y = expf(x.y - m);
    x.z = expf(x.z - m); x.w = expf(x.w - m);
    float s = x.x + x.y + x.z + x.w;
#pragma unroll
    for (int o = 16; o; o >>= 1) s += __shfl_xor_sync(0xffffffffu, s, o);
    if ((t & 31) == 0) red[t >> 5] = s;
    __syncthreads();
    if (t < 8) {
        float ss = red[t];
#pragma unroll
        for (int o = 4; o; o >>= 1) ss += __shfl_xor_sync(0xffu, ss, o);
        red[t] = ss;
    }
    __syncthreads();
    const float inv = 1.0f / red[0];
    x.x *= inv; x.y *= inv; x.z *= inv; x.w *= inv;

    __half2 p0 = __floats2half2_rn(x.x, x.y);
    __half2 p1 = __floats2half2_rn(x.z, x.w);
    *reinterpret_cast<uint2*>(PH(A_P) + row * 2048 + 4 * t) = make_uint2(h2u(p0), h2u(p1));
}

// ---------------------------------------------------------------------------
// Inputs: input, input_mask, W_Q, W_K, W_V, W_O
// ---------------------------------------------------------------------------
extern "C" void kernel_launch(void* const* d_in, const int* in_sizes, int n_in,
                              void* d_out, int out_size)
{
    const float* X  = (const float*)d_in[0];
    const float* WQ = (const float*)d_in[2];
    const float* WK = (const float*)d_in[3];
    const float* WV = (const float*)d_in[4];
    const float* WO = (const float*)d_in[5];
    float* out = (float*)d_out;

    dim3 tb(32, 8);

    // prep: X split; weights transposed + split (offsets passed by value)
    k_splitX<<<4096, 256>>>(X);
    k_splitWT<<<dim3(32, 32, 8), tb>>>(WQ, 1048576, 1024, 1024, A_WQTH, A_WQTL, 1048576);
    k_splitWT<<<dim3(32, 32, 8), tb>>>(WK, 1048576, 1024, 1024, A_WKTH, A_WKTL, 1048576);
    k_splitWT<<<dim3(32, 32, 8), tb>>>(WV, 1048576, 1024, 1024, A_WVTH, A_WVTL, 1048576);
    k_splitWT<<<dim3(32, 256, 1), tb>>>(WO, 0, 1024, 8192, A_WOTH, A_WOTL, 0);

    // projections
    k_qk<<<dim3(8, 32, 16), 256>>>();
    k_v <<<dim3(8, 32,  8), 256>>>();

    // attention
    k_scores <<<dim3(8, 8, 32), 256>>>();
    k_softmax<<<32768, 256>>>();
    k_av     <<<dim3(8, 8, 32), 256>>>();

    // output projection
    k_out<<<dim3(8, 32, 1), 256>>>(out);
}

// round 13
// speedup vs baseline: 1.0564x; 1.0564x over previous
#include <cuda_runtime.h>
#include <cuda_fp16.h>
#include <cstdint>

// ---------------------------------------------------------------------------
// Single 640MB arena (proven-good). Overlays, safe by sequential launch order:
//   [0,16)    Xh ; [16,32) Xl      (dead after k_v)
//   [0,128)   scores fp32 (k_scores overwrites X region) + in-place fp16 probs
//             (softmax rewrites row r at byte 4096*r, first 2KB)
//   [128,192) Qh   [192,256) Ql
//   [256,320) Kh -> Hdh overlay (Kh dead after k_scores)
//   [320,384) Kl
//   [384,448) Vh   [448,512) Vl
//   [512,640) weights: WQh,WQl,WKh,WKl,WVh,WVl,WOh,WOl (16MB each, interleaved)
// ---------------------------------------------------------------------------
__device__ __align__(1024) unsigned char g_arena[(size_t)640 << 20];

#define A_XH   ((size_t)0)
#define A_XL   ((size_t)16  << 20)
#define A_P    ((size_t)0)
#define A_QH   ((size_t)128 << 20)
#define A_QL   ((size_t)192 << 20)
#define A_KH   ((size_t)256 << 20)
#define A_HDH  ((size_t)256 << 20)
#define A_KL   ((size_t)320 << 20)
#define A_VH   ((size_t)384 << 20)
#define A_VL   ((size_t)448 << 20)
#define A_WQH  ((size_t)512 << 20)
#define A_WQL  ((size_t)528 << 20)
#define A_WKH  ((size_t)544 << 20)
#define A_WKL  ((size_t)560 << 20)
#define A_WVH  ((size_t)576 << 20)
#define A_WVL  ((size_t)592 << 20)
#define A_WOH  ((size_t)608 << 20)
#define A_WOL  ((size_t)624 << 20)

__device__ __forceinline__ __half*   PH(size_t o) { return reinterpret_cast<__half*>(g_arena + o); }
__device__ __forceinline__ float*    PF(size_t o) { return reinterpret_cast<float*>(g_arena + o); }
__device__ __forceinline__ uint32_t* PW(size_t o) { return reinterpret_cast<uint32_t*>(g_arena + o); }

// ---------------------------------------------------------------------------
// helpers
// ---------------------------------------------------------------------------
__device__ __forceinline__ void mma_f16(float* d, const uint32_t* a, uint32_t b0, uint32_t b1) {
    asm volatile("mma.sync.aligned.m16n8k16.row.col.f32.f16.f16.f32 "
                 "{%0,%1,%2,%3}, {%4,%5,%6,%7}, {%8,%9}, {%0,%1,%2,%3};"
                 : "+f"(d[0]), "+f"(d[1]), "+f"(d[2]), "+f"(d[3])
                 : "r"(a[0]), "r"(a[1]), "r"(a[2]), "r"(a[3]), "r"(b0), "r"(b1));
}
__device__ __forceinline__ uint32_t h2u(__half2 h) { return *reinterpret_cast<uint32_t*>(&h); }
__device__ __forceinline__ void split_h2(float a, float b, uint32_t& hi, uint32_t& lo) {
    __half2 h = __floats2half2_rn(a, b);
    float2 hf = __half22float2(h);
    __half2 l = __floats2half2_rn(a - hf.x, b - hf.y);
    hi = h2u(h); lo = h2u(l);
}

// ---------------------------------------------------------------------------
// fp16 GEMM: C[128x128]/CTA, Kc=16, m16n8k16, 2-STAGE double-buffered smem.
// Passes: hh always; hl if BLO; lh if ALO.
// BMODE 0: B pre-interleaved words [kp][n] (ldb in words)
// BMODE 1: B plain halves [n][k]   (ldb in halves; producer transposes)
// BMODE 2: B plain halves [k][n]   (ldb in halves; producer PRMT-interleaves)
// EPI 0: fp32 C0;  EPI 1: fp16 hi(C0)+lo(C1);  EPI 2: fp16 hi(C0) only
// One __syncthreads per chunk: STS(i+1) targets the idle stage, whose last
// readers finished before the barrier that ended iteration i-1.
// ---------------------------------------------------------------------------
template <int BMODE, bool ALO, bool BLO, int EPI>
__device__ __forceinline__ void gemm16(
    const __half* __restrict__ Ah, const __half* __restrict__ Al, int lda,
    const void* __restrict__ Bh_, const void* __restrict__ Bl_, int ldb,
    void* __restrict__ C0, void* __restrict__ C1, int ldc,
    int K, float alpha)
{
    __shared__ uint32_t sAh[2][128 * 12];
    __shared__ uint32_t sAl[2][ALO ? 128 * 12 : 4];
    __shared__ uint32_t sBh[2][8 * 136];
    __shared__ uint32_t sBl[2][BLO ? 8 * 136 : 4];

    const int tid = threadIdx.x, lane = tid & 31, wid = tid >> 5;
    const int g = lane >> 2, c = lane & 3;
    const int wm = wid & 1, wn = wid >> 1;
    const int row0 = blockIdx.y * 128, col0 = blockIdx.x * 128;

    const int am = tid >> 1, akh = (tid & 1) * 8;
    const __half* pAh = Ah + (size_t)(row0 + am) * lda + akh;
    const __half* pAl = ALO ? Al + (size_t)(row0 + am) * lda + akh : pAh;

    const uint32_t* pBWh = (const uint32_t*)Bh_;
    const uint32_t* pBWl = (const uint32_t*)Bl_;
    const __half*   pBNh = (const __half*)Bh_;
    const __half*   pBNl = (const __half*)Bl_;
    const __half*   pBVh = (const __half*)Bh_;
    const __half*   pBVl = (const __half*)Bl_;
    if (BMODE == 0) {
        pBWh += (size_t)wid * ldb + col0 + (lane << 2);
        if (BLO) pBWl += (size_t)wid * ldb + col0 + (lane << 2);
    } else if (BMODE == 1) {
        pBNh += (size_t)(col0 + am) * ldb + akh;
        if (BLO) pBNl += (size_t)(col0 + am) * ldb + akh;
    } else {
        pBVh += (size_t)(wid * 2) * ldb + col0 + (lane << 2);
        if (BLO) pBVl += (size_t)(wid * 2) * ldb + col0 + (lane << 2);
    }

    uint4 rAh, rAl, rBh4, rBl4;
    uint2 rV0h, rV1h, rV0l, rV1l;
    const int NC = K >> 4;

    auto ldg = [&](int i) {
        rAh = *reinterpret_cast<const uint4*>(pAh + (size_t)i * 16);
        if (ALO) rAl = *reinterpret_cast<const uint4*>(pAl + (size_t)i * 16);
        if (BMODE == 0) {
            rBh4 = *reinterpret_cast<const uint4*>(pBWh + (size_t)i * 8 * ldb);
            if (BLO) rBl4 = *reinterpret_cast<const uint4*>(pBWl + (size_t)i * 8 * ldb);
        } else if (BMODE == 1) {
            rBh4 = *reinterpret_cast<const uint4*>(pBNh + (size_t)i * 16);
            if (BLO) rBl4 = *reinterpret_cast<const uint4*>(pBNl + (size_t)i * 16);
        } else {
            const __half* b0 = pBVh + (size_t)i * 16 * ldb;
            rV0h = *reinterpret_cast<const uint2*>(b0);
            rV1h = *reinterpret_cast<const uint2*>(b0 + ldb);
            if (BLO) {
                const __half* b1 = pBVl + (size_t)i * 16 * ldb;
                rV0l = *reinterpret_cast<const uint2*>(b1);
                rV1l = *reinterpret_cast<const uint2*>(b1 + ldb);
            }
        }
    };
    auto sts = [&](int st) {
        const int ao = am * 12 + (akh >> 1);
        *reinterpret_cast<uint4*>(&sAh[st][ao]) = rAh;
        if (ALO) *reinterpret_cast<uint4*>(&sAl[st][ao]) = rAl;
        if (BMODE == 0) {
            const int bo = wid * 136 + (lane << 2);
            *reinterpret_cast<uint4*>(&sBh[st][bo]) = rBh4;
            if (BLO) *reinterpret_cast<uint4*>(&sBl[st][bo]) = rBl4;
        } else if (BMODE == 1) {
            const int kj = akh >> 1;
            sBh[st][(kj + 0) * 136 + am] = rBh4.x;
            sBh[st][(kj + 1) * 136 + am] = rBh4.y;
            sBh[st][(kj + 2) * 136 + am] = rBh4.z;
            sBh[st][(kj + 3) * 136 + am] = rBh4.w;
            if (BLO) {
                sBl[st][(kj + 0) * 136 + am] = rBl4.x;
                sBl[st][(kj + 1) * 136 + am] = rBl4.y;
                sBl[st][(kj + 2) * 136 + am] = rBl4.z;
                sBl[st][(kj + 3) * 136 + am] = rBl4.w;
            }
        } else {
            const int bo = wid * 136 + (lane << 2);
            uint4 w;
            w.x = __byte_perm(rV0h.x, rV1h.x, 0x5410);
            w.y = __byte_perm(rV0h.x, rV1h.x, 0x7632);
            w.z = __byte_perm(rV0h.y, rV1h.y, 0x5410);
            w.w = __byte_perm(rV0h.y, rV1h.y, 0x7632);
            *reinterpret_cast<uint4*>(&sBh[st][bo]) = w;
            if (BLO) {
                uint4 u;
                u.x = __byte_perm(rV0l.x, rV1l.x, 0x5410);
                u.y = __byte_perm(rV0l.x, rV1l.x, 0x7632);
                u.z = __byte_perm(rV0l.y, rV1l.y, 0x5410);
                u.w = __byte_perm(rV0l.y, rV1l.y, 0x7632);
                *reinterpret_cast<uint4*>(&sBl[st][bo]) = u;
            }
        }
    };

    float acc[4][4][4];
#pragma unroll
    for (int a = 0; a < 4; a++)
#pragma unroll
        for (int b = 0; b < 4; b++)
#pragma unroll
            for (int d = 0; d < 4; d++) acc[a][b][d] = 0.0f;

    ldg(0); sts(0);
    __syncthreads();

    for (int i = 0; i < NC; i++) {
        const int st = i & 1;
        if (i + 1 < NC) ldg(i + 1);

        uint32_t fbh[4][2], fbl[4][2];
#pragma unroll
        for (int nj = 0; nj < 4; nj++) {
            const int n = wn * 32 + nj * 8 + g;
            fbh[nj][0] = sBh[st][c * 136 + n];
            fbh[nj][1] = sBh[st][(c + 4) * 136 + n];
            if (BLO) {
                fbl[nj][0] = sBl[st][c * 136 + n];
                fbl[nj][1] = sBl[st][(c + 4) * 136 + n];
            }
        }
#pragma unroll
        for (int mi = 0; mi < 4; mi++) {
            const int r = (wm * 64 + mi * 16 + g) * 12 + c;
            uint32_t fa[4], fl[4];
            fa[0] = sAh[st][r];      fa[1] = sAh[st][r + 96];
            fa[2] = sAh[st][r + 4];  fa[3] = sAh[st][r + 100];
            if (ALO) {
                fl[0] = sAl[st][r];      fl[1] = sAl[st][r + 96];
                fl[2] = sAl[st][r + 4];  fl[3] = sAl[st][r + 100];
            }
#pragma unroll
            for (int nj = 0; nj < 4; nj++) {
                mma_f16(acc[mi][nj], fa, fbh[nj][0], fbh[nj][1]);            // hh
                if (BLO) mma_f16(acc[mi][nj], fa, fbl[nj][0], fbl[nj][1]);   // hl
                if (ALO) mma_f16(acc[mi][nj], fl, fbh[nj][0], fbh[nj][1]);   // lh
            }
        }

        if (i + 1 < NC) sts((i + 1) & 1);   // idle stage: safe, last read ended
        __syncthreads();                    // before the barrier closing i-1
    }

#pragma unroll
    for (int mi = 0; mi < 4; mi++) {
        const int r = row0 + wm * 64 + mi * 16 + g;
#pragma unroll
        for (int nj = 0; nj < 4; nj++) {
            const int cc = col0 + wn * 32 + nj * 8 + c * 2;
            float2 v0 = make_float2(acc[mi][nj][0] * alpha, acc[mi][nj][1] * alpha);
            float2 v1 = make_float2(acc[mi][nj][2] * alpha, acc[mi][nj][3] * alpha);
            if (EPI == 0) {
                *reinterpret_cast<float2*>((float*)C0 + (size_t)r * ldc + cc)       = v0;
                *reinterpret_cast<float2*>((float*)C0 + (size_t)(r + 8) * ldc + cc) = v1;
            } else {
                __half2 h0 = __floats2half2_rn(v0.x, v0.y);
                __half2 h1 = __floats2half2_rn(v1.x, v1.y);
                *reinterpret_cast<__half2*>((__half*)C0 + (size_t)r * ldc + cc)       = h0;
                *reinterpret_cast<__half2*>((__half*)C0 + (size_t)(r + 8) * ldc + cc) = h1;
                if (EPI == 1) {
                    float2 f0 = __half22float2(h0), f1 = __half22float2(h1);
                    __half2 l0 = __floats2half2_rn(v0.x - f0.x, v0.y - f0.y);
                    __half2 l1 = __floats2half2_rn(v1.x - f1.x, v1.y - f1.y);
                    *reinterpret_cast<__half2*>((__half*)C1 + (size_t)r * ldc + cc)       = l0;
                    *reinterpret_cast<__half2*>((__half*)C1 + (size_t)(r + 8) * ldc + cc) = l1;
                }
            }
        }
    }
}

// ---------------------------------------------------------------------------
// GEMM wrapper kernels (identical structure to the passing R11)
// ---------------------------------------------------------------------------
__global__ __launch_bounds__(256, 2) void k_qk()
{
    const int z = blockIdx.z, sel = z >> 3, h = z & 7;
    const uint32_t* Wh = PW(sel == 0 ? A_WQH : A_WKH) + (size_t)h * 524288;
    const uint32_t* Wl = PW(sel == 0 ? A_WQL : A_WKL) + (size_t)h * 524288;
    __half* Ch = PH(sel == 0 ? A_QH : A_KH) + (size_t)h * 4194304;
    __half* Cl = PH(sel == 0 ? A_QL : A_KL) + (size_t)h * 4194304;
    gemm16<0, true, true, 1>(PH(A_XH), PH(A_XL), 1024, Wh, Wl, 1024,
                             Ch, Cl, 1024, 1024, 1.0f);
}

__global__ __launch_bounds__(256, 2) void k_v()
{
    const int h = blockIdx.z;
    gemm16<0, false, true, 1>(PH(A_XH), nullptr, 1024,
                              PW(A_WVH) + (size_t)h * 524288,
                              PW(A_WVL) + (size_t)h * 524288, 1024,
                              PH(A_VH) + (size_t)h * 4194304,
                              PH(A_VL) + (size_t)h * 4194304, 1024, 1024, 1.0f);
}

__global__ __launch_bounds__(256, 2) void k_scores()
{
    const size_t z = blockIdx.z;   // h*4 + b
    gemm16<1, true, true, 0>(PH(A_QH) + z * 1048576, PH(A_QL) + z * 1048576, 1024,
                             PH(A_KH) + z * 1048576, PH(A_KL) + z * 1048576, 1024,
                             PF(A_P) + z * 1048576, nullptr, 1024, 1024, 32.0f);
}

__global__ __launch_bounds__(256, 2) void k_av()
{
    const int z = blockIdx.z, h = z >> 2, b = z & 3;
    __half* Ch = PH(A_HDH) + (size_t)b * 8388608 + (size_t)h * 1024;
    gemm16<2, false, true, 2>(PH(A_P) + (size_t)z * 2097152, nullptr, 2048,
                              PH(A_VH) + (size_t)z * 1048576,
                              PH(A_VL) + (size_t)z * 1048576, 1024,
                              Ch, nullptr, 8192, 1024, 1.0f);
}

__global__ __launch_bounds__(256, 2) void k_out(float* __restrict__ out)
{
    gemm16<0, false, true, 0>(PH(A_HDH), nullptr, 8192, PW(A_WOH), PW(A_WOL), 1024,
                              out, nullptr, 1024, 8192, 1.0f);
}

// ---------------------------------------------------------------------------
// prep kernels (host passes byte OFFSETS into the arena)
// ---------------------------------------------------------------------------
__global__ void k_splitX(const float* __restrict__ X)
{
    const int i = blockIdx.x * 256 + threadIdx.x;   // 1M float4
    float4 v = reinterpret_cast<const float4*>(X)[i];
    uint32_t h0, l0, h1, l1;
    split_h2(v.x, v.y, h0, l0);
    split_h2(v.z, v.w, h1, l1);
    reinterpret_cast<uint2*>(PH(A_XH))[i] = make_uint2(h0, h1);
    reinterpret_cast<uint2*>(PH(A_XL))[i] = make_uint2(l0, l1);
}

__global__ void k_splitW(const float* __restrict__ W, size_t zIn,
                         size_t ohOff, size_t olOff, size_t zOut)
{
    uint32_t* oh = PW(ohOff);
    uint32_t* ol = PW(olOff);
    const float* w = W + (size_t)blockIdx.z * zIn;
    const size_t kp = blockIdx.x;
    const int n = threadIdx.x * 4;
    float4 r0 = *reinterpret_cast<const float4*>(w + (2 * kp) * 1024 + n);
    float4 r1 = *reinterpret_cast<const float4*>(w + (2 * kp + 1) * 1024 + n);
    uint4 hw, lw;
    split_h2(r0.x, r1.x, hw.x, lw.x);
    split_h2(r0.y, r1.y, hw.y, lw.y);
    split_h2(r0.z, r1.z, hw.z, lw.z);
    split_h2(r0.w, r1.w, hw.w, lw.w);
    const size_t o = (size_t)blockIdx.z * zOut + kp * 1024 + n;
    *reinterpret_cast<uint4*>(oh + o) = hw;
    *reinterpret_cast<uint4*>(ol + o) = lw;
}

// ---------------------------------------------------------------------------
// softmax: fp32 scores row -> fp16 probs IN PLACE (row r at byte 4096*r)
// ---------------------------------------------------------------------------
__global__ void k_softmax()
{
    __shared__ float red[8];
    const size_t row = blockIdx.x;
    const float* p = PF(A_P) + row * 1024;
    const int t = threadIdx.x;

    float4 x = reinterpret_cast<const float4*>(p)[t];
    float m = fmaxf(fmaxf(x.x, x.y), fmaxf(x.z, x.w));
#pragma unroll
    for (int o = 16; o; o >>= 1) m = fmaxf(m, __shfl_xor_sync(0xffffffffu, m, o));
    if ((t & 31) == 0) red[t >> 5] = m;
    __syncthreads();
    if (t < 8) {
        float mm = red[t];
#pragma unroll
        for (int o = 4; o; o >>= 1) mm = fmaxf(mm, __shfl_xor_sync(0xffu, mm, o));
        red[t] = mm;
    }
    __syncthreads();
    m = red[0];
    __syncthreads();

    x.x = expf(x.x - m); x.y = expf(x.y - m);
    x.z = expf(x.z - m); x.w = expf(x.w - m);
    float s = x.x + x.y + x.z + x.w;
#pragma unroll
    for (int o = 16; o; o >>= 1) s += __shfl_xor_sync(0xffffffffu, s, o);
    if ((t & 31) == 0) red[t >> 5] = s;
    __syncthreads();
    if (t < 8) {
        float ss = red[t];
#pragma unroll
        for (int o = 4; o; o >>= 1) ss += __shfl_xor_sync(0xffu, ss, o);
        red[t] = ss;
    }
    __syncthreads();
    const float inv = 1.0f / red[0];
    x.x *= inv; x.y *= inv; x.z *= inv; x.w *= inv;

    __half2 p0 = __floats2half2_rn(x.x, x.y);
    __half2 p1 = __floats2half2_rn(x.z, x.w);
    *reinterpret_cast<uint2*>(PH(A_P) + row * 2048 + 4 * t) = make_uint2(h2u(p0), h2u(p1));
}

// ---------------------------------------------------------------------------
// Inputs: input, input_mask, W_Q, W_K, W_V, W_O
// ---------------------------------------------------------------------------
extern "C" void kernel_launch(void* const* d_in, const int* in_sizes, int n_in,
                              void* d_out, int out_size)
{
    const float* X  = (const float*)d_in[0];
    const float* WQ = (const float*)d_in[2];
    const float* WK = (const float*)d_in[3];
    const float* WV = (const float*)d_in[4];
    const float* WO = (const float*)d_in[5];
    float* out = (float*)d_out;

    // prep
    k_splitX<<<4096, 256>>>(X);
    k_splitW<<<dim3(512, 1, 8), 256>>>(WQ, 1048576, A_WQH, A_WQL, 524288);
    k_splitW<<<dim3(512, 1, 8), 256>>>(WK, 1048576, A_WKH, A_WKL, 524288);
    k_splitW<<<dim3(512, 1, 8), 256>>>(WV, 1048576, A_WVH, A_WVL, 524288);
    k_splitW<<<dim3(4096, 1, 1), 256>>>(WO, 0, A_WOH, A_WOL, 0);

    // projections
    k_qk<<<dim3(8, 32, 16), 256>>>();
    k_v <<<dim3(8, 32,  8), 256>>>();

    // attention
    k_scores <<<dim3(8, 8, 32), 256>>>();
    k_softmax<<<32768, 256>>>();
    k_av     <<<dim3(8, 8, 32), 256>>>();

    // output projection
    k_out<<<dim3(8, 32, 1), 256>>>(out);
}

// round 14
// speedup vs baseline: 1.2866x; 1.2178x over previous
#include <cuda_runtime.h>
#include <cuda_fp16.h>
#include <cstdint>

// ---------------------------------------------------------------------------
// 608MB arena, NO overlay hazards (every region single-writer before readers):
//   [0,128)   S fp32 scores -> fp16 P in place (row r at byte 4096*r)
//   [128,144) Xh   [144,160) Xl
//   [160,224) Yh   [224,288) Yl          Y = X*M per (h,b), 2MB fp16 each
//   [288,352) VOh  [352,416) VOl         VO = X*M2 per (h,b)
//   [416,432) Mh   [432,448) Ml          M  = W_Q W_K^T per h
//   [448,464) M2h  [464,480) M2l         M2 = W_V W_O_h per h
//   [480,608) plain W splits: WQ h/l, WK h/l, WV h/l, WO h/l (16MB each)
// ---------------------------------------------------------------------------
__device__ __align__(1024) unsigned char g_arena[(size_t)608 << 20];

#define A_P     ((size_t)0)
#define A_XH    ((size_t)128 << 20)
#define A_XL    ((size_t)144 << 20)
#define A_YH    ((size_t)160 << 20)
#define A_YL    ((size_t)224 << 20)
#define A_VOH   ((size_t)288 << 20)
#define A_VOL   ((size_t)352 << 20)
#define A_MH    ((size_t)416 << 20)
#define A_ML    ((size_t)432 << 20)
#define A_M2H   ((size_t)448 << 20)
#define A_M2L   ((size_t)464 << 20)
#define A_WQH   ((size_t)480 << 20)
#define A_WQL   ((size_t)496 << 20)
#define A_WKH   ((size_t)512 << 20)
#define A_WKL   ((size_t)528 << 20)
#define A_WVH   ((size_t)544 << 20)
#define A_WVL   ((size_t)560 << 20)
#define A_WOH   ((size_t)576 << 20)
#define A_WOL   ((size_t)592 << 20)

__device__ __forceinline__ __half* PH(size_t o) { return reinterpret_cast<__half*>(g_arena + o); }
__device__ __forceinline__ float*  PF(size_t o) { return reinterpret_cast<float*>(g_arena + o); }

// ---------------------------------------------------------------------------
// helpers
// ---------------------------------------------------------------------------
__device__ __forceinline__ void mma_f16(float* d, const uint32_t* a, uint32_t b0, uint32_t b1) {
    asm volatile("mma.sync.aligned.m16n8k16.row.col.f32.f16.f16.f32 "
                 "{%0,%1,%2,%3}, {%4,%5,%6,%7}, {%8,%9}, {%0,%1,%2,%3};"
                 : "+f"(d[0]), "+f"(d[1]), "+f"(d[2]), "+f"(d[3])
                 : "r"(a[0]), "r"(a[1]), "r"(a[2]), "r"(a[3]), "r"(b0), "r"(b1));
}
__device__ __forceinline__ uint32_t h2u(__half2 h) { return *reinterpret_cast<uint32_t*>(&h); }
__device__ __forceinline__ void split_h2(float a, float b, uint32_t& hi, uint32_t& lo) {
    __half2 h = __floats2half2_rn(a, b);
    float2 hf = __half22float2(h);
    __half2 l = __floats2half2_rn(a - hf.x, b - hf.y);
    hi = h2u(h); lo = h2u(l);
}

// ---------------------------------------------------------------------------
// fp16 GEMM: C[128x128]/CTA, Kc=16, m16n8k16, single-stage (proven R11 shape).
// Passes: hh always; hl if BLO; lh if ALO.
// AMODE 0: A plain [m][k] halves, lda
// AMODE 1: A = P-concat: k = h*1024+s; row q block (h, b=row0>>10); P row
//          stride 2048 halves, block stride 2097152 halves (hi only)
// BMODE 1: B plain halves [n][k] (producer transposes into smem)
// BMODE 2: B plain halves [k][n] (producer PRMT-interleaves), ldb
// BMODE 3: B = VO-concat: plain [s][n] blocks of 1024x1024, block (h, b),
//          block stride 4*1048576 halves from h, + b*1048576
// EPI 0: fp32 C0;  EPI 1: fp16 hi(C0) + lo(C1)
// ---------------------------------------------------------------------------
template <int AMODE, int BMODE, bool ALO, bool BLO, int EPI>
__device__ __forceinline__ void gemm16(
    const __half* __restrict__ Ah, const __half* __restrict__ Al, int lda,
    const void* __restrict__ Bh_, const void* __restrict__ Bl_, int ldb,
    void* __restrict__ C0, void* __restrict__ C1, int ldc,
    int K, float alpha)
{
    __shared__ uint32_t sAh[128 * 12];
    __shared__ uint32_t sAl[ALO ? 128 * 12 : 4];
    __shared__ uint32_t sBh[8 * 136];
    __shared__ uint32_t sBl[BLO ? 8 * 136 : 4];

    const int tid = threadIdx.x, lane = tid & 31, wid = tid >> 5;
    const int g = lane >> 2, c = lane & 3;
    const int wm = wid & 1, wn = wid >> 1;
    const int row0 = blockIdx.y * 128, col0 = blockIdx.x * 128;
    const int bb = row0 >> 10;                         // batch (concat modes)

    // A producer: row tid>>1, 8 halves at (tid&1)*8
    const int am = tid >> 1, akh = (tid & 1) * 8;
    const __half* pAh;
    const __half* pAl;
    if (AMODE == 0) {
        pAh = Ah + (size_t)(row0 + am) * lda + akh;
        pAl = ALO ? Al + (size_t)(row0 + am) * lda + akh : pAh;
    } else {
        const int q = (row0 + am) & 1023;
        pAh = Ah + (size_t)bb * 2097152 + (size_t)q * 2048 + akh;
        pAl = pAh;
    }

    // B producer pointers
    const __half* pBNh = (const __half*)Bh_;
    const __half* pBNl = (const __half*)Bl_;
    const __half* pBVh = (const __half*)Bh_;
    const __half* pBVl = (const __half*)Bl_;
    if (BMODE == 1) {
        pBNh += (size_t)(col0 + am) * ldb + akh;
        if (BLO) pBNl += (size_t)(col0 + am) * ldb + akh;
    } else if (BMODE == 2) {
        pBVh += (size_t)(wid * 2) * ldb + col0 + (lane << 2);
        if (BLO) pBVl += (size_t)(wid * 2) * ldb + col0 + (lane << 2);
    } else if (BMODE == 3) {
        pBVh += (size_t)bb * 1048576 + (size_t)(wid * 2) * 1024 + col0 + (lane << 2);
        if (BLO) pBVl += (size_t)bb * 1048576 + (size_t)(wid * 2) * 1024 + col0 + (lane << 2);
    }

    uint4 rAh, rAl, rBh4, rBl4;
    uint2 rV0h, rV1h, rV0l, rV1l;
    const int NC = K >> 4;

    auto ldg = [&](int i) {
        if (AMODE == 0) {
            rAh = *reinterpret_cast<const uint4*>(pAh + (size_t)i * 16);
            if (ALO) rAl = *reinterpret_cast<const uint4*>(pAl + (size_t)i * 16);
        } else {
            const __half* a = pAh + (size_t)(i >> 6) * 8388608 + (size_t)(i & 63) * 16;
            rAh = *reinterpret_cast<const uint4*>(a);
        }
        if (BMODE == 1) {
            rBh4 = *reinterpret_cast<const uint4*>(pBNh + (size_t)i * 16);
            if (BLO) rBl4 = *reinterpret_cast<const uint4*>(pBNl + (size_t)i * 16);
        } else if (BMODE == 2) {
            const __half* b0 = pBVh + (size_t)i * 16 * ldb;
            rV0h = *reinterpret_cast<const uint2*>(b0);
            rV1h = *reinterpret_cast<const uint2*>(b0 + ldb);
            if (BLO) {
                const __half* b1 = pBVl + (size_t)i * 16 * ldb;
                rV0l = *reinterpret_cast<const uint2*>(b1);
                rV1l = *reinterpret_cast<const uint2*>(b1 + ldb);
            }
        } else {
            const size_t off = (size_t)(i >> 6) * 4194304 + (size_t)(i & 63) * 16384;
            const __half* b0 = pBVh + off;
            rV0h = *reinterpret_cast<const uint2*>(b0);
            rV1h = *reinterpret_cast<const uint2*>(b0 + 1024);
            if (BLO) {
                const __half* b1 = pBVl + off;
                rV0l = *reinterpret_cast<const uint2*>(b1);
                rV1l = *reinterpret_cast<const uint2*>(b1 + 1024);
            }
        }
    };
    auto sts = [&]() {
        const int ao = am * 12 + (akh >> 1);
        *reinterpret_cast<uint4*>(&sAh[ao]) = rAh;
        if (ALO) *reinterpret_cast<uint4*>(&sAl[ao]) = rAl;
        if (BMODE == 1) {
            const int kj = akh >> 1;
            sBh[(kj + 0) * 136 + am] = rBh4.x;
            sBh[(kj + 1) * 136 + am] = rBh4.y;
            sBh[(kj + 2) * 136 + am] = rBh4.z;
            sBh[(kj + 3) * 136 + am] = rBh4.w;
            if (BLO) {
                sBl[(kj + 0) * 136 + am] = rBl4.x;
                sBl[(kj + 1) * 136 + am] = rBl4.y;
                sBl[(kj + 2) * 136 + am] = rBl4.z;
                sBl[(kj + 3) * 136 + am] = rBl4.w;
            }
        } else {
            const int bo = wid * 136 + (lane << 2);
            uint4 w;
            w.x = __byte_perm(rV0h.x, rV1h.x, 0x5410);
            w.y = __byte_perm(rV0h.x, rV1h.x, 0x7632);
            w.z = __byte_perm(rV0h.y, rV1h.y, 0x5410);
            w.w = __byte_perm(rV0h.y, rV1h.y, 0x7632);
            *reinterpret_cast<uint4*>(&sBh[bo]) = w;
            if (BLO) {
                uint4 u;
                u.x = __byte_perm(rV0l.x, rV1l.x, 0x5410);
                u.y = __byte_perm(rV0l.x, rV1l.x, 0x7632);
                u.z = __byte_perm(rV0l.y, rV1l.y, 0x5410);
                u.w = __byte_perm(rV0l.y, rV1l.y, 0x7632);
                *reinterpret_cast<uint4*>(&sBl[bo]) = u;
            }
        }
    };

    float acc[4][4][4];
#pragma unroll
    for (int a = 0; a < 4; a++)
#pragma unroll
        for (int b = 0; b < 4; b++)
#pragma unroll
            for (int d = 0; d < 4; d++) acc[a][b][d] = 0.0f;

    ldg(0);
    for (int i = 0; i < NC; i++) {
        sts();
        __syncthreads();
        if (i + 1 < NC) ldg(i + 1);

        uint32_t fbh[4][2], fbl[4][2];
#pragma unroll
        for (int nj = 0; nj < 4; nj++) {
            const int n = wn * 32 + nj * 8 + g;
            fbh[nj][0] = sBh[c * 136 + n];
            fbh[nj][1] = sBh[(c + 4) * 136 + n];
            if (BLO) {
                fbl[nj][0] = sBl[c * 136 + n];
                fbl[nj][1] = sBl[(c + 4) * 136 + n];
            }
        }
#pragma unroll
        for (int mi = 0; mi < 4; mi++) {
            const int r = (wm * 64 + mi * 16 + g) * 12 + c;
            uint32_t fa[4], fl[4];
            fa[0] = sAh[r];      fa[1] = sAh[r + 96];
            fa[2] = sAh[r + 4];  fa[3] = sAh[r + 100];
            if (ALO) {
                fl[0] = sAl[r];      fl[1] = sAl[r + 96];
                fl[2] = sAl[r + 4];  fl[3] = sAl[r + 100];
            }
#pragma unroll
            for (int nj = 0; nj < 4; nj++) {
                mma_f16(acc[mi][nj], fa, fbh[nj][0], fbh[nj][1]);            // hh
                if (BLO) mma_f16(acc[mi][nj], fa, fbl[nj][0], fbl[nj][1]);   // hl
                if (ALO) mma_f16(acc[mi][nj], fl, fbh[nj][0], fbh[nj][1]);   // lh
            }
        }
        __syncthreads();
    }

    // epilogue
#pragma unroll
    for (int mi = 0; mi < 4; mi++) {
        const int r = row0 + wm * 64 + mi * 16 + g;
#pragma unroll
        for (int nj = 0; nj < 4; nj++) {
            const int cc = col0 + wn * 32 + nj * 8 + c * 2;
            float2 v0 = make_float2(acc[mi][nj][0] * alpha, acc[mi][nj][1] * alpha);
            float2 v1 = make_float2(acc[mi][nj][2] * alpha, acc[mi][nj][3] * alpha);
            if (EPI == 0) {
                *reinterpret_cast<float2*>((float*)C0 + (size_t)r * ldc + cc)       = v0;
                *reinterpret_cast<float2*>((float*)C0 + (size_t)(r + 8) * ldc + cc) = v1;
            } else {
                __half2 h0 = __floats2half2_rn(v0.x, v0.y);
                __half2 h1 = __floats2half2_rn(v1.x, v1.y);
                *reinterpret_cast<__half2*>((__half*)C0 + (size_t)r * ldc + cc)       = h0;
                *reinterpret_cast<__half2*>((__half*)C0 + (size_t)(r + 8) * ldc + cc) = h1;
                float2 f0 = __half22float2(h0), f1 = __half22float2(h1);
                __half2 l0 = __floats2half2_rn(v0.x - f0.x, v0.y - f0.y);
                __half2 l1 = __floats2half2_rn(v1.x - f1.x, v1.y - f1.y);
                *reinterpret_cast<__half2*>((__half*)C1 + (size_t)r * ldc + cc)       = l0;
                *reinterpret_cast<__half2*>((__half*)C1 + (size_t)(r + 8) * ldc + cc) = l1;
            }
        }
    }
}

// ---------------------------------------------------------------------------
// GEMM wrapper kernels
// ---------------------------------------------------------------------------
// M_h = W_Q_h @ W_K_h^T   (3-pass; feeds the score path)
__global__ __launch_bounds__(256, 2) void k_m()
{
    const size_t h = blockIdx.z;
    gemm16<0, 1, true, true, 1>(PH(A_WQH) + h * 1048576, PH(A_WQL) + h * 1048576, 1024,
                                PH(A_WKH) + h * 1048576, PH(A_WKL) + h * 1048576, 1024,
                                PH(A_MH) + h * 1048576, PH(A_ML) + h * 1048576, 1024,
                                1024, 1.0f);
}

// M2_h = W_V_h @ W_O_h   (2-pass; value path)
__global__ __launch_bounds__(256, 2) void k_m2()
{
    const size_t h = blockIdx.z;
    gemm16<0, 2, false, true, 1>(PH(A_WVH) + h * 1048576, nullptr, 1024,
                                 PH(A_WOH) + h * 1048576, PH(A_WOL) + h * 1048576, 1024,
                                 PH(A_M2H) + h * 1048576, PH(A_M2L) + h * 1048576, 1024,
                                 1024, 1.0f);
}

// Y_hb = X_b @ M_h   (3-pass)
__global__ __launch_bounds__(256, 2) void k_y()
{
    const size_t z = blockIdx.z, h = z >> 2, b = z & 3;
    gemm16<0, 2, true, true, 1>(PH(A_XH) + b * 1048576, PH(A_XL) + b * 1048576, 1024,
                                PH(A_MH) + h * 1048576, PH(A_ML) + h * 1048576, 1024,
                                PH(A_YH) + z * 1048576, PH(A_YL) + z * 1048576, 1024,
                                1024, 1.0f);
}

// VO_hb = X_b @ M2_h   (2-pass)
__global__ __launch_bounds__(256, 2) void k_vo()
{
    const size_t z = blockIdx.z, h = z >> 2, b = z & 3;
    gemm16<0, 2, false, true, 1>(PH(A_XH) + b * 1048576, nullptr, 1024,
                                 PH(A_M2H) + h * 1048576, PH(A_M2L) + h * 1048576, 1024,
                                 PH(A_VOH) + z * 1048576, PH(A_VOL) + z * 1048576, 1024,
                                 1024, 1.0f);
}

// S_hb = 32 * Y_hb @ X_b^T   (3-pass, fp32 out)
__global__ __launch_bounds__(256, 2) void k_s()
{
    const size_t z = blockIdx.z, b = z & 3;
    gemm16<0, 1, true, true, 0>(PH(A_YH) + z * 1048576, PH(A_YL) + z * 1048576, 1024,
                                PH(A_XH) + b * 1048576, PH(A_XL) + b * 1048576, 1024,
                                PF(A_P) + z * 1048576, nullptr, 1024,
                                1024, 32.0f);   // sqrt(1024)
}

// out = sum_h P_hb @ VO_hb   (concat-K GEMM, K = 8192; P hi-only, VO 2-pass)
__global__ __launch_bounds__(256, 2) void k_out(float* __restrict__ out)
{
    gemm16<1, 3, false, true, 0>(PH(A_P), nullptr, 0,
                                 PH(A_VOH), PH(A_VOL), 0,
                                 out, nullptr, 1024, 8192, 1.0f);
}

// ---------------------------------------------------------------------------
// prep: generic elementwise fp32 -> fp16 hi/lo split (plain layout)
// ---------------------------------------------------------------------------
__global__ void k_split(const float* __restrict__ src, size_t ohOff, size_t olOff)
{
    const size_t i = (size_t)blockIdx.x * 256 + threadIdx.x;
    float4 v = reinterpret_cast<const float4*>(src)[i];
    uint32_t h0, l0, h1, l1;
    split_h2(v.x, v.y, h0, l0);
    split_h2(v.z, v.w, h1, l1);
    reinterpret_cast<uint2*>(PH(ohOff))[i] = make_uint2(h0, h1);
    reinterpret_cast<uint2*>(PH(olOff))[i] = make_uint2(l0, l1);
}

// ---------------------------------------------------------------------------
// softmax: fp32 scores row -> fp16 probs IN PLACE (row r at byte 4096*r)
// ---------------------------------------------------------------------------
__global__ void k_softmax()
{
    __shared__ float red[8];
    const size_t row = blockIdx.x;
    const float* p = PF(A_P) + row * 1024;
    const int t = threadIdx.x;

    float4 x = reinterpret_cast<const float4*>(p)[t];
    float m = fmaxf(fmaxf(x.x, x.y), fmaxf(x.z, x.w));
#pragma unroll
    for (int o = 16; o; o >>= 1) m = fmaxf(m, __shfl_xor_sync(0xffffffffu, m, o));
    if ((t & 31) == 0) red[t >> 5] = m;
    __syncthreads();
    if (t < 8) {
        float mm = red[t];
#pragma unroll
        for (int o = 4; o; o >>= 1) mm = fmaxf(mm, __shfl_xor_sync(0xffu, mm, o));
        red[t] = mm;
    }
    __syncthreads();
    m = red[0];
    __syncthreads();

    x.x = expf(x.x - m); x.y = expf(x.y - m);
    x.z = expf(x.z - m); x.w = expf(x.w - m);
    float s = x.x + x.y + x.z + x.w;
#pragma unroll
    for (int o = 16; o; o >>= 1) s += __shfl_xor_sync(0xffffffffu, s, o);
    if ((t & 31) == 0) red[t >> 5] = s;
    __syncthreads();
    if (t < 8) {
        float ss = red[t];
#pragma unroll
        for (int o = 4; o; o >>= 1) ss += __shfl_xor_sync(0xffu, ss, o);
        red[t] = ss;
    }
    __syncthreads();
    const float inv = 1.0f / red[0];
    x.x *= inv; x.y *= inv; x.z *= inv; x.w *= inv;

    __half2 p0 = __floats2half2_rn(x.x, x.y);
    __half2 p1 = __floats2half2_rn(x.z, x.w);
    *reinterpret_cast<uint2*>(PH(A_P) + row * 2048 + 4 * t) = make_uint2(h2u(p0), h2u(p1));
}

// ---------------------------------------------------------------------------
// Inputs: input, input_mask, W_Q, W_K, W_V, W_O
// ---------------------------------------------------------------------------
extern "C" void kernel_launch(void* const* d_in, const int* in_sizes, int n_in,
                              void* d_out, int out_size)
{
    const float* X  = (const float*)d_in[0];
    const float* WQ = (const float*)d_in[2];
    const float* WK = (const float*)d_in[3];
    const float* WV = (const float*)d_in[4];
    const float* WO = (const float*)d_in[5];
    float* out = (float*)d_out;

    // prep: plain elementwise hi/lo splits
    k_split<<<4096, 256>>>(X,  A_XH,  A_XL);
    k_split<<<8192, 256>>>(WQ, A_WQH, A_WQL);
    k_split<<<8192, 256>>>(WK, A_WKH, A_WKL);
    k_split<<<8192, 256>>>(WV, A_WVH, A_WVL);
    k_split<<<8192, 256>>>(WO, A_WOH, A_WOL);

    // weight-weight products (tiny)
    k_m <<<dim3(8, 8, 8), 256>>>();
    k_m2<<<dim3(8, 8, 8), 256>>>();

    // per-(h,b) projections through combined matrices
    k_y <<<dim3(8, 8, 32), 256>>>();
    k_vo<<<dim3(8, 8, 32), 256>>>();

    // attention
    k_s      <<<dim3(8, 8, 32), 256>>>();
    k_softmax<<<32768, 256>>>();

    // fused P@VO with concatenated K (replaces k_av + k_out)
    k_out<<<dim3(8, 32), 256>>>(out);
}

// round 15
// speedup vs baseline: 1.5223x; 1.1832x over previous
#include <cuda_runtime.h>
#include <cuda_fp16.h>
#include <cstdint>

// ---------------------------------------------------------------------------
// 608MB arena (≤ proven 640MB limit). Regions (single writer before readers):
//   [0,128)   S fp32 scores -> fp16 P in place (row r at byte 4096*r)
//   [128,144) Xh   [144,160) Xl
//   [160,224) Yh   [224,288) Yl          Y = X*M per (h,b)
//   [288,352) VOh  (lo no longer needed) VO = X*M2 per (h,b)
//   [416,432) Mh   [432,448) Ml          M  = W_Q W_K^T per h (22-bit pair)
//   [448,464) M2h                        M2 = W_V W_O_h per h (hi only)
//   [480,608) plain W splits: WQ h/l, WK h/l, WV h/l, WO h/l (16MB each)
// ---------------------------------------------------------------------------
__device__ __align__(1024) unsigned char g_arena[(size_t)608 << 20];

#define A_P     ((size_t)0)
#define A_XH    ((size_t)128 << 20)
#define A_XL    ((size_t)144 << 20)
#define A_YH    ((size_t)160 << 20)
#define A_YL    ((size_t)224 << 20)
#define A_VOH   ((size_t)288 << 20)
#define A_MH    ((size_t)416 << 20)
#define A_ML    ((size_t)432 << 20)
#define A_M2H   ((size_t)448 << 20)
#define A_WQH   ((size_t)480 << 20)
#define A_WQL   ((size_t)496 << 20)
#define A_WKH   ((size_t)512 << 20)
#define A_WKL   ((size_t)528 << 20)
#define A_WVH   ((size_t)544 << 20)
#define A_WVL   ((size_t)560 << 20)
#define A_WOH   ((size_t)576 << 20)
#define A_WOL   ((size_t)592 << 20)

__device__ __forceinline__ __half* PH(size_t o) { return reinterpret_cast<__half*>(g_arena + o); }
__device__ __forceinline__ float*  PF(size_t o) { return reinterpret_cast<float*>(g_arena + o); }

// ---------------------------------------------------------------------------
// helpers
// ---------------------------------------------------------------------------
__device__ __forceinline__ void mma_f16(float* d, const uint32_t* a, uint32_t b0, uint32_t b1) {
    asm volatile("mma.sync.aligned.m16n8k16.row.col.f32.f16.f16.f32 "
                 "{%0,%1,%2,%3}, {%4,%5,%6,%7}, {%8,%9}, {%0,%1,%2,%3};"
                 : "+f"(d[0]), "+f"(d[1]), "+f"(d[2]), "+f"(d[3])
                 : "r"(a[0]), "r"(a[1]), "r"(a[2]), "r"(a[3]), "r"(b0), "r"(b1));
}
__device__ __forceinline__ uint32_t h2u(__half2 h) { return *reinterpret_cast<uint32_t*>(&h); }
__device__ __forceinline__ void split_h2(float a, float b, uint32_t& hi, uint32_t& lo) {
    __half2 h = __floats2half2_rn(a, b);
    float2 hf = __half22float2(h);
    __half2 l = __floats2half2_rn(a - hf.x, b - hf.y);
    hi = h2u(h); lo = h2u(l);
}

// ---------------------------------------------------------------------------
// fp16 GEMM: C[128x128]/CTA, Kc=16, m16n8k16, single-stage (proven R14 shape).
// Passes: hh always; hl if BLO; lh if ALO.
// AMODE 0: A plain [m][k] halves, lda
// AMODE 1: A = P-concat: k = h*1024+s; batch b = row0>>10; P row stride 2048
// BMODE 1: B plain halves [n][k] (producer transposes into smem)
// BMODE 2: B plain halves [k][n] (producer PRMT-interleaves), ldb
// BMODE 3: B = VO-concat: [s][n] blocks of 1024x1024, h-stride 4M, + b*1M
// EPI 0: fp32 C0;  EPI 1: fp16 hi(C0)+lo(C1);  EPI 2: fp16 hi(C0) only
// ---------------------------------------------------------------------------
template <int AMODE, int BMODE, bool ALO, bool BLO, int EPI>
__device__ __forceinline__ void gemm16(
    const __half* __restrict__ Ah, const __half* __restrict__ Al, int lda,
    const void* __restrict__ Bh_, const void* __restrict__ Bl_, int ldb,
    void* __restrict__ C0, void* __restrict__ C1, int ldc,
    int K, float alpha)
{
    __shared__ uint32_t sAh[128 * 12];
    __shared__ uint32_t sAl[ALO ? 128 * 12 : 4];
    __shared__ uint32_t sBh[8 * 136];
    __shared__ uint32_t sBl[BLO ? 8 * 136 : 4];

    const int tid = threadIdx.x, lane = tid & 31, wid = tid >> 5;
    const int g = lane >> 2, c = lane & 3;
    const int wm = wid & 1, wn = wid >> 1;
    const int row0 = blockIdx.y * 128, col0 = blockIdx.x * 128;
    const int bb = row0 >> 10;

    const int am = tid >> 1, akh = (tid & 1) * 8;
    const __half* pAh;
    const __half* pAl;
    if (AMODE == 0) {
        pAh = Ah + (size_t)(row0 + am) * lda + akh;
        pAl = ALO ? Al + (size_t)(row0 + am) * lda + akh : pAh;
    } else {
        const int q = (row0 + am) & 1023;
        pAh = Ah + (size_t)bb * 2097152 + (size_t)q * 2048 + akh;
        pAl = pAh;
    }

    const __half* pBNh = (const __half*)Bh_;
    const __half* pBNl = (const __half*)Bl_;
    const __half* pBVh = (const __half*)Bh_;
    const __half* pBVl = (const __half*)Bl_;
    if (BMODE == 1) {
        pBNh += (size_t)(col0 + am) * ldb + akh;
        if (BLO) pBNl += (size_t)(col0 + am) * ldb + akh;
    } else if (BMODE == 2) {
        pBVh += (size_t)(wid * 2) * ldb + col0 + (lane << 2);
        if (BLO) pBVl += (size_t)(wid * 2) * ldb + col0 + (lane << 2);
    } else if (BMODE == 3) {
        pBVh += (size_t)bb * 1048576 + (size_t)(wid * 2) * 1024 + col0 + (lane << 2);
        if (BLO) pBVl += (size_t)bb * 1048576 + (size_t)(wid * 2) * 1024 + col0 + (lane << 2);
    }

    uint4 rAh, rAl, rBh4, rBl4;
    uint2 rV0h, rV1h, rV0l, rV1l;
    const int NC = K >> 4;

    auto ldg = [&](int i) {
        if (AMODE == 0) {
            rAh = *reinterpret_cast<const uint4*>(pAh + (size_t)i * 16);
            if (ALO) rAl = *reinterpret_cast<const uint4*>(pAl + (size_t)i * 16);
        } else {
            const __half* a = pAh + (size_t)(i >> 6) * 8388608 + (size_t)(i & 63) * 16;
            rAh = *reinterpret_cast<const uint4*>(a);
        }
        if (BMODE == 1) {
            rBh4 = *reinterpret_cast<const uint4*>(pBNh + (size_t)i * 16);
            if (BLO) rBl4 = *reinterpret_cast<const uint4*>(pBNl + (size_t)i * 16);
        } else if (BMODE == 2) {
            const __half* b0 = pBVh + (size_t)i * 16 * ldb;
            rV0h = *reinterpret_cast<const uint2*>(b0);
            rV1h = *reinterpret_cast<const uint2*>(b0 + ldb);
            if (BLO) {
                const __half* b1 = pBVl + (size_t)i * 16 * ldb;
                rV0l = *reinterpret_cast<const uint2*>(b1);
                rV1l = *reinterpret_cast<const uint2*>(b1 + ldb);
            }
        } else {
            const size_t off = (size_t)(i >> 6) * 4194304 + (size_t)(i & 63) * 16384;
            const __half* b0 = pBVh + off;
            rV0h = *reinterpret_cast<const uint2*>(b0);
            rV1h = *reinterpret_cast<const uint2*>(b0 + 1024);
            if (BLO) {
                const __half* b1 = pBVl + off;
                rV0l = *reinterpret_cast<const uint2*>(b1);
                rV1l = *reinterpret_cast<const uint2*>(b1 + 1024);
            }
        }
    };
    auto sts = [&]() {
        const int ao = am * 12 + (akh >> 1);
        *reinterpret_cast<uint4*>(&sAh[ao]) = rAh;
        if (ALO) *reinterpret_cast<uint4*>(&sAl[ao]) = rAl;
        if (BMODE == 1) {
            const int kj = akh >> 1;
            sBh[(kj + 0) * 136 + am] = rBh4.x;
            sBh[(kj + 1) * 136 + am] = rBh4.y;
            sBh[(kj + 2) * 136 + am] = rBh4.z;
            sBh[(kj + 3) * 136 + am] = rBh4.w;
            if (BLO) {
                sBl[(kj + 0) * 136 + am] = rBl4.x;
                sBl[(kj + 1) * 136 + am] = rBl4.y;
                sBl[(kj + 2) * 136 + am] = rBl4.z;
                sBl[(kj + 3) * 136 + am] = rBl4.w;
            }
        } else {
            const int bo = wid * 136 + (lane << 2);
            uint4 w;
            w.x = __byte_perm(rV0h.x, rV1h.x, 0x5410);
            w.y = __byte_perm(rV0h.x, rV1h.x, 0x7632);
            w.z = __byte_perm(rV0h.y, rV1h.y, 0x5410);
            w.w = __byte_perm(rV0h.y, rV1h.y, 0x7632);
            *reinterpret_cast<uint4*>(&sBh[bo]) = w;
            if (BLO) {
                uint4 u;
                u.x = __byte_perm(rV0l.x, rV1l.x, 0x5410);
                u.y = __byte_perm(rV0l.x, rV1l.x, 0x7632);
                u.z = __byte_perm(rV0l.y, rV1l.y, 0x5410);
                u.w = __byte_perm(rV0l.y, rV1l.y, 0x7632);
                *reinterpret_cast<uint4*>(&sBl[bo]) = u;
            }
        }
    };

    float acc[4][4][4];
#pragma unroll
    for (int a = 0; a < 4; a++)
#pragma unroll
        for (int b = 0; b < 4; b++)
#pragma unroll
            for (int d = 0; d < 4; d++) acc[a][b][d] = 0.0f;

    ldg(0);
    for (int i = 0; i < NC; i++) {
        sts();
        __syncthreads();
        if (i + 1 < NC) ldg(i + 1);

        uint32_t fbh[4][2], fbl[4][2];
#pragma unroll
        for (int nj = 0; nj < 4; nj++) {
            const int n = wn * 32 + nj * 8 + g;
            fbh[nj][0] = sBh[c * 136 + n];
            fbh[nj][1] = sBh[(c + 4) * 136 + n];
            if (BLO) {
                fbl[nj][0] = sBl[c * 136 + n];
                fbl[nj][1] = sBl[(c + 4) * 136 + n];
            }
        }
#pragma unroll
        for (int mi = 0; mi < 4; mi++) {
            const int r = (wm * 64 + mi * 16 + g) * 12 + c;
            uint32_t fa[4], fl[4];
            fa[0] = sAh[r];      fa[1] = sAh[r + 96];
            fa[2] = sAh[r + 4];  fa[3] = sAh[r + 100];
            if (ALO) {
                fl[0] = sAl[r];      fl[1] = sAl[r + 96];
                fl[2] = sAl[r + 4];  fl[3] = sAl[r + 100];
            }
#pragma unroll
            for (int nj = 0; nj < 4; nj++) {
                mma_f16(acc[mi][nj], fa, fbh[nj][0], fbh[nj][1]);            // hh
                if (BLO) mma_f16(acc[mi][nj], fa, fbl[nj][0], fbl[nj][1]);   // hl
                if (ALO) mma_f16(acc[mi][nj], fl, fbh[nj][0], fbh[nj][1]);   // lh
            }
        }
        __syncthreads();
    }

    // epilogue
#pragma unroll
    for (int mi = 0; mi < 4; mi++) {
        const int r = row0 + wm * 64 + mi * 16 + g;
#pragma unroll
        for (int nj = 0; nj < 4; nj++) {
            const int cc = col0 + wn * 32 + nj * 8 + c * 2;
            float2 v0 = make_float2(acc[mi][nj][0] * alpha, acc[mi][nj][1] * alpha);
            float2 v1 = make_float2(acc[mi][nj][2] * alpha, acc[mi][nj][3] * alpha);
            if (EPI == 0) {
                *reinterpret_cast<float2*>((float*)C0 + (size_t)r * ldc + cc)       = v0;
                *reinterpret_cast<float2*>((float*)C0 + (size_t)(r + 8) * ldc + cc) = v1;
            } else {
                __half2 h0 = __floats2half2_rn(v0.x, v0.y);
                __half2 h1 = __floats2half2_rn(v1.x, v1.y);
                *reinterpret_cast<__half2*>((__half*)C0 + (size_t)r * ldc + cc)       = h0;
                *reinterpret_cast<__half2*>((__half*)C0 + (size_t)(r + 8) * ldc + cc) = h1;
                if (EPI == 1) {
                    float2 f0 = __half22float2(h0), f1 = __half22float2(h1);
                    __half2 l0 = __floats2half2_rn(v0.x - f0.x, v0.y - f0.y);
                    __half2 l1 = __floats2half2_rn(v1.x - f1.x, v1.y - f1.y);
                    *reinterpret_cast<__half2*>((__half*)C1 + (size_t)r * ldc + cc)       = l0;
                    *reinterpret_cast<__half2*>((__half*)C1 + (size_t)(r + 8) * ldc + cc) = l1;
                }
            }
        }
    }
}

// ---------------------------------------------------------------------------
// GEMM wrapper kernels (merged for launch packing)
// ---------------------------------------------------------------------------
// z<8: M_h = WQ_h @ WK_h^T (3-pass, hi+lo out — score path needs 22 bits)
// z>=8: M2_h = WV_h @ WO_h (1-pass, hi out — value path, fp16 storage anyway)
__global__ __launch_bounds__(256, 2) void k_mm()
{
    const int z = blockIdx.z;
    if (z < 8) {
        const size_t h = z;
        gemm16<0, 1, true, true, 1>(PH(A_WQH) + h * 1048576, PH(A_WQL) + h * 1048576, 1024,
                                    PH(A_WKH) + h * 1048576, PH(A_WKL) + h * 1048576, 1024,
                                    PH(A_MH) + h * 1048576, PH(A_ML) + h * 1048576, 1024,
                                    1024, 1.0f);
    } else {
        const size_t h = z - 8;
        gemm16<0, 2, false, false, 2>(PH(A_WVH) + h * 1048576, nullptr, 1024,
                                      PH(A_WOH) + h * 1048576, nullptr, 1024,
                                      PH(A_M2H) + h * 1048576, nullptr, 1024,
                                      1024, 1.0f);
    }
}

// z<32: Y_hb = X_b @ M_h (3-pass, hi+lo out)
// z>=32: VO_hb = X_b @ M2_h (1-pass, hi out)
__global__ __launch_bounds__(256, 2) void k_yvo()
{
    const int z = blockIdx.z;
    if (z < 32) {
        const size_t h = z >> 2, b = z & 3;
        gemm16<0, 2, true, true, 1>(PH(A_XH) + b * 1048576, PH(A_XL) + b * 1048576, 1024,
                                    PH(A_MH) + h * 1048576, PH(A_ML) + h * 1048576, 1024,
                                    PH(A_YH) + (size_t)z * 1048576,
                                    PH(A_YL) + (size_t)z * 1048576, 1024, 1024, 1.0f);
    } else {
        const size_t zz = z - 32, h = zz >> 2, b = zz & 3;
        gemm16<0, 2, false, false, 2>(PH(A_XH) + b * 1048576, nullptr, 1024,
                                      PH(A_M2H) + h * 1048576, nullptr, 1024,
                                      PH(A_VOH) + zz * 1048576, nullptr, 1024,
                                      1024, 1.0f);
    }
}

// S_hb = 32 * Y_hb @ X_b^T (3-pass, fp32 out)
__global__ __launch_bounds__(256, 2) void k_s()
{
    const size_t z = blockIdx.z, b = z & 3;
    gemm16<0, 1, true, true, 0>(PH(A_YH) + z * 1048576, PH(A_YL) + z * 1048576, 1024,
                                PH(A_XH) + b * 1048576, PH(A_XL) + b * 1048576, 1024,
                                PF(A_P) + z * 1048576, nullptr, 1024,
                                1024, 32.0f);   // sqrt(1024)
}

// out = sum_h P_hb @ VO_hb   (concat-K GEMM K=8192, 1-pass hh)
__global__ __launch_bounds__(256, 2) void k_out(float* __restrict__ out)
{
    gemm16<1, 3, false, false, 0>(PH(A_P), nullptr, 0,
                                  PH(A_VOH), nullptr, 0,
                                  out, nullptr, 1024, 8192, 1.0f);
}

// ---------------------------------------------------------------------------
// merged prep: 5 hi/lo splits in one launch (grid.y selects tensor)
// ---------------------------------------------------------------------------
__global__ void k_split5(const float* __restrict__ X,  const float* __restrict__ WQ,
                         const float* __restrict__ WK, const float* __restrict__ WV,
                         const float* __restrict__ WO)
{
    const float* src;
    size_t oh, ol;
    int nblk;
    switch (blockIdx.y) {
    case 0:  src = X;  oh = A_XH;  ol = A_XL;  nblk = 4096; break;
    case 1:  src = WQ; oh = A_WQH; ol = A_WQL; nblk = 8192; break;
    case 2:  src = WK; oh = A_WKH; ol = A_WKL; nblk = 8192; break;
    case 3:  src = WV; oh = A_WVH; ol = A_WVL; nblk = 8192; break;
    default: src = WO; oh = A_WOH; ol = A_WOL; nblk = 8192; break;
    }
    if ((int)blockIdx.x >= nblk) return;
    const size_t i = (size_t)blockIdx.x * 256 + threadIdx.x;
    float4 v = reinterpret_cast<const float4*>(src)[i];
    uint32_t h0, l0, h1, l1;
    split_h2(v.x, v.y, h0, l0);
    split_h2(v.z, v.w, h1, l1);
    reinterpret_cast<uint2*>(PH(oh))[i] = make_uint2(h0, h1);
    reinterpret_cast<uint2*>(PH(ol))[i] = make_uint2(l0, l1);
}

// ---------------------------------------------------------------------------
// softmax: fp32 scores row -> fp16 probs IN PLACE (row r at byte 4096*r)
// ---------------------------------------------------------------------------
__global__ void k_softmax()
{
    __shared__ float red[8];
    const size_t row = blockIdx.x;
    const float* p = PF(A_P) + row * 1024;
    const int t = threadIdx.x;

    float4 x = reinterpret_cast<const float4*>(p)[t];
    float m = fmaxf(fmaxf(x.x, x.y), fmaxf(x.z, x.w));
#pragma unroll
    for (int o = 16; o; o >>= 1) m = fmaxf(m, __shfl_xor_sync(0xffffffffu, m, o));
    if ((t & 31) == 0) red[t >> 5] = m;
    __syncthreads();
    if (t < 8) {
        float mm = red[t];
#pragma unroll
        for (int o = 4; o; o >>= 1) mm = fmaxf(mm, __shfl_xor_sync(0xffu, mm, o));
        red[t] = mm;
    }
    __syncthreads();
    m = red[0];
    __syncthreads();

    x.x = expf(x.x - m); x.y = expf(x.y - m);
    x.z = expf(x.z - m); x.w = expf(x.w - m);
    float s = x.x + x.y + x.z + x.w;
#pragma unroll
    for (int o = 16; o; o >>= 1) s += __shfl_xor_sync(0xffffffffu, s, o);
    if ((t & 31) == 0) red[t >> 5] = s;
    __syncthreads();
    if (t < 8) {
        float ss = red[t];
#pragma unroll
        for (int o = 4; o; o >>= 1) ss += __shfl_xor_sync(0xffu, ss, o);
        red[t] = ss;
    }
    __syncthreads();
    const float inv = 1.0f / red[0];
    x.x *= inv; x.y *= inv; x.z *= inv; x.w *= inv;

    __half2 p0 = __floats2half2_rn(x.x, x.y);
    __half2 p1 = __floats2half2_rn(x.z, x.w);
    *reinterpret_cast<uint2*>(PH(A_P) + row * 2048 + 4 * t) = make_uint2(h2u(p0), h2u(p1));
}

// ---------------------------------------------------------------------------
// Inputs: input, input_mask, W_Q, W_K, W_V, W_O
// ---------------------------------------------------------------------------
extern "C" void kernel_launch(void* const* d_in, const int* in_sizes, int n_in,
                              void* d_out, int out_size)
{
    const float* X  = (const float*)d_in[0];
    const float* WQ = (const float*)d_in[2];
    const float* WK = (const float*)d_in[3];
    const float* WV = (const float*)d_in[4];
    const float* WO = (const float*)d_in[5];
    float* out = (float*)d_out;

    k_split5<<<dim3(8192, 5), 256>>>(X, WQ, WK, WV, WO);
    k_mm    <<<dim3(8, 8, 16), 256>>>();
    k_yvo   <<<dim3(8, 8, 64), 256>>>();
    k_s     <<<dim3(8, 8, 32), 256>>>();
    k_softmax<<<32768, 256>>>();
    k_out   <<<dim3(8, 32), 256>>>(out);
}